// round 15
// baseline (speedup 1.0000x reference)
#include <cuda_runtime.h>
#include <cuda_fp16.h>
#include <cstdint>

#define M_NODES 100000
#define K_IN    256
#define N_OUT   128
#define MAX_E   1600000
#define SCAN_BS 1024

// ---- static device scratch (no allocs allowed) ----
__device__ __half    g_support_h[(size_t)M_NODES * N_OUT];  // 25.6 MB fp16
__device__ uint32_t  g_Wh[(K_IN / 2) * N_OUT];              // W packed half2 (k-pairs)
__device__ int       g_cnt[M_NODES];
__device__ int       g_start[M_NODES + 1];
__device__ int       g_rank[MAX_E];                         // per-edge rank within row
__device__ uint2     g_edges[MAX_E];                        // packed (col, val_bits)
__device__ unsigned long long g_desc[128];                  // lookback descriptors
__device__ int       g_parity;                              // toggled by hist each launch

__device__ __forceinline__ uint32_t pack_h2(float lo, float hi)
{
    uint32_t r;
    asm("cvt.rn.f16x2.f32 %0, %1, %2;" : "=r"(r) : "f"(hi), "f"(lo));
    return r;
}

__device__ __forceinline__ void cp_async16(uint32_t saddr, const void* gptr, int srcBytes)
{
    asm volatile("cp.async.cg.shared.global [%0], [%1], 16, %2;\n"
                 :: "r"(saddr), "l"(gptr), "r"(srcBytes));
}
#define CP_COMMIT()  asm volatile("cp.async.commit_group;\n" ::)
#define CP_WAIT(N)   asm volatile("cp.async.wait_group %0;\n" :: "n"(N))

// ---------------------------------------------------------------------------
// Kernel 0: W -> packed half2, layout [k/2][n]  (verified R12)
// ---------------------------------------------------------------------------
__global__ void wconv_kernel(const float* __restrict__ W)
{
    int i = blockIdx.x * blockDim.x + threadIdx.x;
    if (i < (K_IN / 2) * N_OUT) {
        int kp = i / N_OUT, n = i % N_OUT;
        g_Wh[i] = pack_h2(W[(2 * kp) * N_OUT + n], W[(2 * kp + 1) * N_OUT + n]);
    }
}

// ---------------------------------------------------------------------------
// Kernel 1: support = x @ W + b  via FP16 mma.sync.m16n8k16
// CTA tile 64(M) x 128(N), warp tile 16x64 -> 32 acc regs -> 3 CTAs/SM.
// 3-stage cp.async pipeline with wait_group 1 (verified R14 structure).
// ---------------------------------------------------------------------------
__global__ __launch_bounds__(256, 3) void gemm_fp16_kernel(
    const float* __restrict__ x,
    const float* __restrict__ bias)
{
    extern __shared__ float smf[];
    float*    Asf = smf;                             // [3][64][40] fp32
    uint32_t* Bsf = (uint32_t*)(smf + 3 * 64 * 40);  // [3][16][136] half2

    const int tid   = threadIdx.x;
    const int lane  = tid & 31;
    const int wid   = tid >> 5;
    const int warpM = wid & 3;     // 16-row slice
    const int warpN = wid >> 2;    // 64-col slice
    const int g     = lane >> 2;
    const int tg    = lane & 3;
    const int rowBase = blockIdx.x * 64;

    float acc[8][4];
    #pragma unroll
    for (int nt = 0; nt < 8; nt++)
        #pragma unroll
        for (int r = 0; r < 4; r++) acc[nt][r] = 0.f;

    const uint32_t aBase[3] = {
        (uint32_t)__cvta_generic_to_shared(Asf),
        (uint32_t)__cvta_generic_to_shared(Asf + 64 * 40),
        (uint32_t)__cvta_generic_to_shared(Asf + 2 * 64 * 40) };
    const uint32_t bBase[3] = {
        (uint32_t)__cvta_generic_to_shared(Bsf),
        (uint32_t)__cvta_generic_to_shared(Bsf + 16 * 136),
        (uint32_t)__cvta_generic_to_shared(Bsf + 2 * 16 * 136) };

    auto loadStage = [&](int kb, int s) {
        // A tile: 64 rows x 32 k fp32 = 512 x 16B, 2 per thread
        #pragma unroll
        for (int i = 0; i < 2; i++) {
            int idx  = tid + i * 256;
            int row  = idx >> 3;             // 0..63
            int k4   = (idx & 7) * 4;
            int grow = rowBase + row;
            int sz   = (grow < M_NODES) ? 16 : 0;
            const float* src = x + (size_t)min(grow, M_NODES - 1) * K_IN + kb + k4;
            cp_async16(aBase[s] + (uint32_t)(row * 40 + k4) * 4, src, sz);
        }
        // B tile: 16 kpair-rows x 128 n half2 = 512 x 16B, 2 per thread
        #pragma unroll
        for (int i = 0; i < 2; i++) {
            int idx = tid + i * 256;
            int kp  = idx >> 5;
            int n4  = (idx & 31) * 4;
            cp_async16(bBase[s] + (uint32_t)(kp * 136 + n4) * 4,
                       g_Wh + (kb / 2 + kp) * N_OUT + n4, 16);
        }
        CP_COMMIT();
    };

    auto compute = [&](int s) {
        const float*    A = Asf + s * 64 * 40;
        const uint32_t* B = Bsf + s * 16 * 136;
        #pragma unroll
        for (int ks = 0; ks < 2; ks++) {
            const int kk = ks * 16;
            const int kp = ks * 8;
            uint32_t bfr[8][2];
            #pragma unroll
            for (int nt = 0; nt < 8; nt++) {
                int col = warpN * 64 + nt * 8 + g;
                bfr[nt][0] = B[(kp + tg) * 136 + col];
                bfr[nt][1] = B[(kp + 4 + tg) * 136 + col];
            }
            int r0 = warpM * 16 + g;
            const float* Ar0 = A + r0 * 40 + kk;
            const float* Ar1 = A + (r0 + 8) * 40 + kk;
            float2 f0 = *(const float2*)(Ar0 + 2 * tg);
            float2 f1 = *(const float2*)(Ar1 + 2 * tg);
            float2 f2 = *(const float2*)(Ar0 + 2 * tg + 8);
            float2 f3 = *(const float2*)(Ar1 + 2 * tg + 8);
            uint32_t a0 = pack_h2(f0.x, f0.y);
            uint32_t a1 = pack_h2(f1.x, f1.y);
            uint32_t a2 = pack_h2(f2.x, f2.y);
            uint32_t a3 = pack_h2(f3.x, f3.y);
            #pragma unroll
            for (int nt = 0; nt < 8; nt++) {
                asm volatile(
                    "mma.sync.aligned.m16n8k16.row.col.f32.f16.f16.f32 "
                    "{%0,%1,%2,%3}, {%4,%5,%6,%7}, {%8,%9}, {%0,%1,%2,%3};"
                    : "+f"(acc[nt][0]), "+f"(acc[nt][1]),
                      "+f"(acc[nt][2]), "+f"(acc[nt][3])
                    : "r"(a0), "r"(a1), "r"(a2), "r"(a3),
                      "r"(bfr[nt][0]), "r"(bfr[nt][1]));
            }
        }
    };

    // prologue: two stages in flight
    loadStage(0, 0);
    loadStage(32, 1);
    CP_WAIT(1);
    __syncthreads();

    #pragma unroll
    for (int kb = 0; kb < 8; kb++) {
        if (kb + 2 < 8) loadStage((kb + 2) * 32, (kb + 2) % 3);
        compute(kb % 3);
        if (kb + 1 < 8) {
            if (kb + 2 < 8) CP_WAIT(1);
            else            CP_WAIT(0);
            __syncthreads();
        }
    }

    #pragma unroll
    for (int nt = 0; nt < 8; nt++) {
        int col = warpN * 64 + nt * 8 + tg * 2;
        float2 bv = *(const float2*)(bias + col);
        int row0 = rowBase + warpM * 16 + g;
        if (row0 < M_NODES) {
            __half2 h = __floats2half2_rn(acc[nt][0] + bv.x,
                                          acc[nt][1] + bv.y);
            *(__half2*)(g_support_h + (size_t)row0 * N_OUT + col) = h;
        }
        int row1 = row0 + 8;
        if (row1 < M_NODES) {
            __half2 h = __floats2half2_rn(acc[nt][2] + bv.x,
                                          acc[nt][3] + bv.y);
            *(__half2*)(g_support_h + (size_t)row1 * N_OUT + col) = h;
        }
    }
}

// ---------------------------------------------------------------------------
// CSR build: hist(+rank) -> lookback scan -> permute (verified R12)
// ---------------------------------------------------------------------------
__global__ void hist_kernel(const int* __restrict__ erow, int E)
{
    if (blockIdx.x == 0 && threadIdx.x == 0) g_parity ^= 1;
    int i = blockIdx.x * blockDim.x + threadIdx.x;
    if (i < E) g_rank[i] = atomicAdd(&g_cnt[erow[i]], 1);
}

__device__ __forceinline__ int warp_incl_scan(int v, int lane)
{
    #pragma unroll
    for (int off = 1; off < 32; off <<= 1) {
        int t = __shfl_up_sync(0xffffffffu, v, off);
        if (lane >= off) v += t;
    }
    return v;
}

__device__ __forceinline__ int warp_sum_bcast(int v)
{
    #pragma unroll
    for (int off = 16; off; off >>= 1) v += __shfl_down_sync(0xffffffffu, v, off);
    return __shfl_sync(0xffffffffu, v, 0);
}

__global__ __launch_bounds__(SCAN_BS) void scan_lookback_kernel(int n, int E)
{
    __shared__ int wsum[32];
    __shared__ int s_bex;
    const int bid  = blockIdx.x;
    const int i    = bid * SCAN_BS + threadIdx.x;
    const int lane = threadIdx.x & 31;
    const int w    = threadIdx.x >> 5;

    const int parity = g_parity;
    const unsigned codeAGG = (unsigned)(2 * parity + 1);
    const unsigned codeINC = (unsigned)(2 * parity + 2);

    int v = (i < n) ? g_cnt[i] : 0;
    if (i < n) g_cnt[i] = 0;

    int incl = warp_incl_scan(v, lane);
    if (lane == 31) wsum[w] = incl;
    __syncthreads();
    int total = 0;
    if (w == 0) {
        int s  = wsum[lane];
        int ws = warp_incl_scan(s, lane);
        total  = __shfl_sync(0xffffffffu, ws, 31);
        wsum[lane] = ws - s;
        if (lane == 0) {
            unsigned long long pk = ((unsigned long long)codeAGG << 32)
                                  | (unsigned long long)(unsigned)total;
            *(volatile unsigned long long*)(g_desc + bid) = pk;
        }
    }
    __syncthreads();

    if (w == 0) {
        int bex = 0;
        int base = bid - 1;
        while (base >= 0) {
            int idx = base - lane;
            unsigned long long pk = 0;
            unsigned code = 0;
            if (idx >= 0) {
                do {
                    pk   = *(volatile unsigned long long*)(g_desc + idx);
                    code = (unsigned)(pk >> 32);
                } while (code != codeAGG && code != codeINC);
            }
            int  val   = (int)(unsigned)pk;
            bool isinc = (idx >= 0) && (code == codeINC);
            unsigned mask = __ballot_sync(0xffffffffu, isinc);
            if (mask) {
                int stop = __ffs(mask) - 1;
                int c = (idx >= 0 && lane <= stop) ? val : 0;
                bex += warp_sum_bcast(c);
                break;
            } else {
                int c = (idx >= 0) ? val : 0;
                bex += warp_sum_bcast(c);
                base -= 32;
            }
        }
        if (lane == 0) {
            unsigned long long pk = ((unsigned long long)codeINC << 32)
                                  | (unsigned long long)(unsigned)(bex + total);
            *(volatile unsigned long long*)(g_desc + bid) = pk;
            s_bex = bex;
        }
    }
    __syncthreads();

    if (i < n) g_start[i] = s_bex + wsum[w] + incl - v;
    if (bid == gridDim.x - 1 && threadIdx.x == 0) g_start[n] = E;
}

__global__ void permute_kernel(const int* __restrict__ erow,
                               const int* __restrict__ ecol,
                               const float* __restrict__ eval, int E)
{
    int i = blockIdx.x * blockDim.x + threadIdx.x;
    if (i < E) {
        int pos = g_start[erow[i]] + g_rank[i];
        g_edges[pos] = make_uint2((unsigned)ecol[i], __float_as_uint(eval[i]));
    }
}

// ---------------------------------------------------------------------------
// Gather: one warp per row, lane owns 4 features (verified R9/R12)
// ---------------------------------------------------------------------------
__global__ __launch_bounds__(256) void gather_kernel(float* __restrict__ out)
{
    int row  = (blockIdx.x * blockDim.x + threadIdx.x) >> 5;
    int lane = threadIdx.x & 31;
    if (row >= M_NODES) return;

    int s = g_start[row];
    int e = g_start[row + 1];

    const uint2* sup = (const uint2*)g_support_h;

    float4 acc0 = make_float4(0.f, 0.f, 0.f, 0.f);
    float4 acc1 = make_float4(0.f, 0.f, 0.f, 0.f);

    int j = s;
    for (; j + 8 <= e; j += 8) {
        uint2 ee[8], dd[8];
        #pragma unroll
        for (int q = 0; q < 8; q++) ee[q] = __ldg(&g_edges[j + q]);
        #pragma unroll
        for (int q = 0; q < 8; q++) dd[q] = __ldg(&sup[(size_t)ee[q].x * 32 + lane]);
        #pragma unroll
        for (int q = 0; q < 8; q++) {
            float v = __uint_as_float(ee[q].y);
            float2 a = __half22float2(*(__half2*)&dd[q].x);
            float2 b = __half22float2(*(__half2*)&dd[q].y);
            if (q & 1) {
                acc1.x += v * a.x; acc1.y += v * a.y;
                acc1.z += v * b.x; acc1.w += v * b.y;
            } else {
                acc0.x += v * a.x; acc0.y += v * a.y;
                acc0.z += v * b.x; acc0.w += v * b.y;
            }
        }
    }
    if (j + 4 <= e) {
        uint2 ee[4], dd[4];
        #pragma unroll
        for (int q = 0; q < 4; q++) ee[q] = __ldg(&g_edges[j + q]);
        #pragma unroll
        for (int q = 0; q < 4; q++) dd[q] = __ldg(&sup[(size_t)ee[q].x * 32 + lane]);
        #pragma unroll
        for (int q = 0; q < 4; q++) {
            float v = __uint_as_float(ee[q].y);
            float2 a = __half22float2(*(__half2*)&dd[q].x);
            float2 b = __half22float2(*(__half2*)&dd[q].y);
            if (q & 1) {
                acc1.x += v * a.x; acc1.y += v * a.y;
                acc1.z += v * b.x; acc1.w += v * b.y;
            } else {
                acc0.x += v * a.x; acc0.y += v * a.y;
                acc0.z += v * b.x; acc0.w += v * b.y;
            }
        }
        j += 4;
    }
    for (; j < e; j++) {
        uint2 e0 = __ldg(&g_edges[j]);
        uint2 d0 = __ldg(&sup[(size_t)e0.x * 32 + lane]);
        float v0 = __uint_as_float(e0.y);
        float2 a = __half22float2(*(__half2*)&d0.x);
        float2 b = __half22float2(*(__half2*)&d0.y);
        acc0.x += v0 * a.x; acc0.y += v0 * a.y; acc0.z += v0 * b.x; acc0.w += v0 * b.y;
    }

    float4 o;
    o.x = fmaxf(acc0.x + acc1.x, 0.f);
    o.y = fmaxf(acc0.y + acc1.y, 0.f);
    o.z = fmaxf(acc0.z + acc1.z, 0.f);
    o.w = fmaxf(acc0.w + acc1.w, 0.f);
    __stcs((float4*)(out + (size_t)row * N_OUT) + lane, o);
}

// ---------------------------------------------------------------------------
// Side stream + fork/join events, created once at load time.
// ---------------------------------------------------------------------------
static cudaStream_t g_s2   = nullptr;
static cudaEvent_t  g_fork = nullptr;
static cudaEvent_t  g_join = nullptr;
namespace {
struct StreamInit {
    StreamInit() {
        if (cudaStreamCreateWithFlags(&g_s2, cudaStreamNonBlocking) != cudaSuccess) g_s2 = nullptr;
        if (cudaEventCreateWithFlags(&g_fork, cudaEventDisableTiming) != cudaSuccess) g_fork = nullptr;
        if (cudaEventCreateWithFlags(&g_join, cudaEventDisableTiming) != cudaSuccess) g_join = nullptr;
    }
};
static StreamInit g_streamInit;
}

// ---------------------------------------------------------------------------
extern "C" void kernel_launch(void* const* d_in, const int* in_sizes, int n_in,
                              void* d_out, int out_size)
{
    const float* x    = (const float*)d_in[0];
    const int*   erow = (const int*)  d_in[1];
    const int*   ecol = (const int*)  d_in[2];
    const float* eval = (const float*)d_in[3];
    const float* W    = (const float*)d_in[4];
    const float* bias = (const float*)d_in[5];
    float* out = (float*)d_out;

    const int E  = in_sizes[1];
    const int nb = (M_NODES + SCAN_BS - 1) / SCAN_BS;   // 98

    const int GEMM_SMEM = (3 * 64 * 40 + 3 * 16 * 136) * 4;   // 56832 B
    cudaFuncSetAttribute(gemm_fp16_kernel,
                         cudaFuncAttributeMaxDynamicSharedMemorySize, GEMM_SMEM);

    const bool fork = (g_s2 && g_fork && g_join);
    cudaStream_t s2 = fork ? g_s2 : (cudaStream_t)0;

    if (fork) {
        cudaEventRecord(g_fork, 0);
        cudaStreamWaitEvent(s2, g_fork, 0);
    }

    // ---- branch A (side stream): CSR build ----
    hist_kernel<<<(E + 255) / 256, 256, 0, s2>>>(erow, E);
    scan_lookback_kernel<<<nb, SCAN_BS, 0, s2>>>(M_NODES, E);
    permute_kernel<<<(E + 255) / 256, 256, 0, s2>>>(erow, ecol, eval, E);

    if (fork) cudaEventRecord(g_join, s2);

    // ---- branch B (main stream): GEMM ----
    wconv_kernel<<<((K_IN / 2) * N_OUT + 255) / 256, 256>>>(W);
    gemm_fp16_kernel<<<(M_NODES + 63) / 64, 256, GEMM_SMEM>>>(x, bias);

    // ---- join, then gather ----
    if (fork) cudaStreamWaitEvent(0, g_join, 0);
    gather_kernel<<<(M_NODES * 32 + 255) / 256, 256>>>(out);
}

// round 16
// speedup vs baseline: 1.0608x; 1.0608x over previous
#include <cuda_runtime.h>
#include <cuda_fp16.h>
#include <cstdint>

#define M_NODES 100000
#define K_IN    256
#define N_OUT   128
#define MAX_E   1600000
#define SCAN_BS 1024

// ---- static device scratch (no allocs allowed) ----
__device__ __half    g_support_h[(size_t)M_NODES * N_OUT];  // 25.6 MB fp16
__device__ uint32_t  g_Wh[(K_IN / 2) * N_OUT];              // W packed half2 (k-pairs)
__device__ int       g_cnt[M_NODES];
__device__ int       g_start[M_NODES + 1];
__device__ int       g_rank[MAX_E];                         // per-edge rank within row
__device__ uint2     g_edges[MAX_E];                        // packed (col, val_bits)
__device__ unsigned long long g_desc[128];                  // lookback descriptors
__device__ int       g_parity;                              // toggled by hist each launch

__device__ __forceinline__ uint32_t pack_h2(float lo, float hi)
{
    uint32_t r;
    asm("cvt.rn.f16x2.f32 %0, %1, %2;" : "=r"(r) : "f"(hi), "f"(lo));
    return r;
}

__device__ __forceinline__ void cp_async16(uint32_t saddr, const void* gptr, int srcBytes)
{
    asm volatile("cp.async.cg.shared.global [%0], [%1], 16, %2;\n"
                 :: "r"(saddr), "l"(gptr), "r"(srcBytes));
}
#define CP_COMMIT()  asm volatile("cp.async.commit_group;\n" ::)
#define CP_WAIT(N)   asm volatile("cp.async.wait_group %0;\n" :: "n"(N))

// ---------------------------------------------------------------------------
// Kernel 0: W -> packed half2, layout [k/2][n]  (verified R12)
// ---------------------------------------------------------------------------
__global__ void wconv_kernel(const float* __restrict__ W)
{
    int i = blockIdx.x * blockDim.x + threadIdx.x;
    if (i < (K_IN / 2) * N_OUT) {
        int kp = i / N_OUT, n = i % N_OUT;
        g_Wh[i] = pack_h2(W[(2 * kp) * N_OUT + n], W[(2 * kp + 1) * N_OUT + n]);
    }
}

// ---------------------------------------------------------------------------
// Kernel 1: support = x @ W + b  via FP16 mma.sync.m16n8k16
// 128x128 CTA tile, 3-stage cp.async pipeline, wait_group 1 (verified R14).
// ---------------------------------------------------------------------------
__global__ __launch_bounds__(256) void gemm_fp16_kernel(
    const float* __restrict__ x,
    const float* __restrict__ bias)
{
    extern __shared__ float smf[];
    float*    Asf = smf;                              // [3][128][40] fp32
    uint32_t* Bsf = (uint32_t*)(smf + 3 * 128 * 40);  // [3][16][136] half2

    const int tid   = threadIdx.x;
    const int lane  = tid & 31;
    const int wid   = tid >> 5;
    const int warpM = wid & 3;
    const int warpN = wid >> 2;
    const int g     = lane >> 2;
    const int tg    = lane & 3;
    const int rowBase = blockIdx.x * 128;

    float acc[2][8][4];
    #pragma unroll
    for (int mt = 0; mt < 2; mt++)
        #pragma unroll
        for (int nt = 0; nt < 8; nt++)
            #pragma unroll
            for (int r = 0; r < 4; r++) acc[mt][nt][r] = 0.f;

    const uint32_t aBase[3] = {
        (uint32_t)__cvta_generic_to_shared(Asf),
        (uint32_t)__cvta_generic_to_shared(Asf + 128 * 40),
        (uint32_t)__cvta_generic_to_shared(Asf + 2 * 128 * 40) };
    const uint32_t bBase[3] = {
        (uint32_t)__cvta_generic_to_shared(Bsf),
        (uint32_t)__cvta_generic_to_shared(Bsf + 16 * 136),
        (uint32_t)__cvta_generic_to_shared(Bsf + 2 * 16 * 136) };

    auto loadStage = [&](int kb, int s) {
        #pragma unroll
        for (int i = 0; i < 4; i++) {
            int idx  = tid + i * 256;
            int row  = idx >> 3;
            int k4   = (idx & 7) * 4;
            int grow = rowBase + row;
            int sz   = (grow < M_NODES) ? 16 : 0;
            const float* src = x + (size_t)min(grow, M_NODES - 1) * K_IN + kb + k4;
            cp_async16(aBase[s] + (uint32_t)(row * 40 + k4) * 4, src, sz);
        }
        #pragma unroll
        for (int i = 0; i < 2; i++) {
            int idx = tid + i * 256;
            int kp  = idx >> 5;
            int n4  = (idx & 31) * 4;
            cp_async16(bBase[s] + (uint32_t)(kp * 136 + n4) * 4,
                       g_Wh + (kb / 2 + kp) * N_OUT + n4, 16);
        }
        CP_COMMIT();
    };

    auto compute = [&](int s) {
        const float*    A = Asf + s * 128 * 40;
        const uint32_t* B = Bsf + s * 16 * 136;
        #pragma unroll
        for (int ks = 0; ks < 2; ks++) {
            const int kk = ks * 16;
            const int kp = ks * 8;
            uint32_t bfr[8][2];
            #pragma unroll
            for (int nt = 0; nt < 8; nt++) {
                int col = warpN * 64 + nt * 8 + g;
                bfr[nt][0] = B[(kp + tg) * 136 + col];
                bfr[nt][1] = B[(kp + 4 + tg) * 136 + col];
            }
            #pragma unroll
            for (int mt = 0; mt < 2; mt++) {
                int r0 = warpM * 32 + mt * 16 + g;
                const float* Ar0 = A + r0 * 40 + kk;
                const float* Ar1 = A + (r0 + 8) * 40 + kk;
                float2 f0 = *(const float2*)(Ar0 + 2 * tg);
                float2 f1 = *(const float2*)(Ar1 + 2 * tg);
                float2 f2 = *(const float2*)(Ar0 + 2 * tg + 8);
                float2 f3 = *(const float2*)(Ar1 + 2 * tg + 8);
                uint32_t a0 = pack_h2(f0.x, f0.y);
                uint32_t a1 = pack_h2(f1.x, f1.y);
                uint32_t a2 = pack_h2(f2.x, f2.y);
                uint32_t a3 = pack_h2(f3.x, f3.y);
                #pragma unroll
                for (int nt = 0; nt < 8; nt++) {
                    asm volatile(
                        "mma.sync.aligned.m16n8k16.row.col.f32.f16.f16.f32 "
                        "{%0,%1,%2,%3}, {%4,%5,%6,%7}, {%8,%9}, {%0,%1,%2,%3};"
                        : "+f"(acc[mt][nt][0]), "+f"(acc[mt][nt][1]),
                          "+f"(acc[mt][nt][2]), "+f"(acc[mt][nt][3])
                        : "r"(a0), "r"(a1), "r"(a2), "r"(a3),
                          "r"(bfr[nt][0]), "r"(bfr[nt][1]));
                }
            }
        }
    };

    loadStage(0, 0);
    loadStage(32, 1);
    CP_WAIT(1);
    __syncthreads();

    #pragma unroll
    for (int kb = 0; kb < 8; kb++) {
        if (kb + 2 < 8) loadStage((kb + 2) * 32, (kb + 2) % 3);
        compute(kb % 3);
        if (kb + 1 < 8) {
            if (kb + 2 < 8) CP_WAIT(1);
            else            CP_WAIT(0);
            __syncthreads();
        }
    }

    #pragma unroll
    for (int nt = 0; nt < 8; nt++) {
        int col = warpN * 64 + nt * 8 + tg * 2;
        float2 bv = *(const float2*)(bias + col);
        #pragma unroll
        for (int mt = 0; mt < 2; mt++) {
            int row0 = rowBase + warpM * 32 + mt * 16 + g;
            if (row0 < M_NODES) {
                __half2 h = __floats2half2_rn(acc[mt][nt][0] + bv.x,
                                              acc[mt][nt][1] + bv.y);
                *(__half2*)(g_support_h + (size_t)row0 * N_OUT + col) = h;
            }
            int row1 = row0 + 8;
            if (row1 < M_NODES) {
                __half2 h = __floats2half2_rn(acc[mt][nt][2] + bv.x,
                                              acc[mt][nt][3] + bv.y);
                *(__half2*)(g_support_h + (size_t)row1 * N_OUT + col) = h;
            }
        }
    }
}

// ---------------------------------------------------------------------------
// CSR build: hist(+rank) -> lookback scan -> permute (verified R12)
// ---------------------------------------------------------------------------
__global__ void hist_kernel(const int* __restrict__ erow, int E)
{
    if (blockIdx.x == 0 && threadIdx.x == 0) g_parity ^= 1;
    int i = blockIdx.x * blockDim.x + threadIdx.x;
    if (i < E) g_rank[i] = atomicAdd(&g_cnt[erow[i]], 1);
}

__device__ __forceinline__ int warp_incl_scan(int v, int lane)
{
    #pragma unroll
    for (int off = 1; off < 32; off <<= 1) {
        int t = __shfl_up_sync(0xffffffffu, v, off);
        if (lane >= off) v += t;
    }
    return v;
}

__device__ __forceinline__ int warp_sum_bcast(int v)
{
    #pragma unroll
    for (int off = 16; off; off >>= 1) v += __shfl_down_sync(0xffffffffu, v, off);
    return __shfl_sync(0xffffffffu, v, 0);
}

__global__ __launch_bounds__(SCAN_BS) void scan_lookback_kernel(int n, int E)
{
    __shared__ int wsum[32];
    __shared__ int s_bex;
    const int bid  = blockIdx.x;
    const int i    = bid * SCAN_BS + threadIdx.x;
    const int lane = threadIdx.x & 31;
    const int w    = threadIdx.x >> 5;

    const int parity = g_parity;
    const unsigned codeAGG = (unsigned)(2 * parity + 1);
    const unsigned codeINC = (unsigned)(2 * parity + 2);

    int v = (i < n) ? g_cnt[i] : 0;
    if (i < n) g_cnt[i] = 0;

    int incl = warp_incl_scan(v, lane);
    if (lane == 31) wsum[w] = incl;
    __syncthreads();
    int total = 0;
    if (w == 0) {
        int s  = wsum[lane];
        int ws = warp_incl_scan(s, lane);
        total  = __shfl_sync(0xffffffffu, ws, 31);
        wsum[lane] = ws - s;
        if (lane == 0) {
            unsigned long long pk = ((unsigned long long)codeAGG << 32)
                                  | (unsigned long long)(unsigned)total;
            *(volatile unsigned long long*)(g_desc + bid) = pk;
        }
    }
    __syncthreads();

    if (w == 0) {
        int bex = 0;
        int base = bid - 1;
        while (base >= 0) {
            int idx = base - lane;
            unsigned long long pk = 0;
            unsigned code = 0;
            if (idx >= 0) {
                do {
                    pk   = *(volatile unsigned long long*)(g_desc + idx);
                    code = (unsigned)(pk >> 32);
                } while (code != codeAGG && code != codeINC);
            }
            int  val   = (int)(unsigned)pk;
            bool isinc = (idx >= 0) && (code == codeINC);
            unsigned mask = __ballot_sync(0xffffffffu, isinc);
            if (mask) {
                int stop = __ffs(mask) - 1;
                int c = (idx >= 0 && lane <= stop) ? val : 0;
                bex += warp_sum_bcast(c);
                break;
            } else {
                int c = (idx >= 0) ? val : 0;
                bex += warp_sum_bcast(c);
                base -= 32;
            }
        }
        if (lane == 0) {
            unsigned long long pk = ((unsigned long long)codeINC << 32)
                                  | (unsigned long long)(unsigned)(bex + total);
            *(volatile unsigned long long*)(g_desc + bid) = pk;
            s_bex = bex;
        }
    }
    __syncthreads();

    if (i < n) g_start[i] = s_bex + wsum[w] + incl - v;
    if (bid == gridDim.x - 1 && threadIdx.x == 0) g_start[n] = E;
}

__global__ void permute_kernel(const int* __restrict__ erow,
                               const int* __restrict__ ecol,
                               const float* __restrict__ eval, int E)
{
    int i = blockIdx.x * blockDim.x + threadIdx.x;
    if (i < E) {
        int pos = g_start[erow[i]] + g_rank[i];
        g_edges[pos] = make_uint2((unsigned)ecol[i], __float_as_uint(eval[i]));
    }
}

// ---------------------------------------------------------------------------
// Gather: one warp per row, lane owns 4 features (verified R9/R12)
// ---------------------------------------------------------------------------
__global__ __launch_bounds__(256) void gather_kernel(float* __restrict__ out)
{
    int row  = (blockIdx.x * blockDim.x + threadIdx.x) >> 5;
    int lane = threadIdx.x & 31;
    if (row >= M_NODES) return;

    int s = g_start[row];
    int e = g_start[row + 1];

    const uint2* sup = (const uint2*)g_support_h;

    float4 acc0 = make_float4(0.f, 0.f, 0.f, 0.f);
    float4 acc1 = make_float4(0.f, 0.f, 0.f, 0.f);

    int j = s;
    for (; j + 8 <= e; j += 8) {
        uint2 ee[8], dd[8];
        #pragma unroll
        for (int q = 0; q < 8; q++) ee[q] = __ldg(&g_edges[j + q]);
        #pragma unroll
        for (int q = 0; q < 8; q++) dd[q] = __ldg(&sup[(size_t)ee[q].x * 32 + lane]);
        #pragma unroll
        for (int q = 0; q < 8; q++) {
            float v = __uint_as_float(ee[q].y);
            float2 a = __half22float2(*(__half2*)&dd[q].x);
            float2 b = __half22float2(*(__half2*)&dd[q].y);
            if (q & 1) {
                acc1.x += v * a.x; acc1.y += v * a.y;
                acc1.z += v * b.x; acc1.w += v * b.y;
            } else {
                acc0.x += v * a.x; acc0.y += v * a.y;
                acc0.z += v * b.x; acc0.w += v * b.y;
            }
        }
    }
    if (j + 4 <= e) {
        uint2 ee[4], dd[4];
        #pragma unroll
        for (int q = 0; q < 4; q++) ee[q] = __ldg(&g_edges[j + q]);
        #pragma unroll
        for (int q = 0; q < 4; q++) dd[q] = __ldg(&sup[(size_t)ee[q].x * 32 + lane]);
        #pragma unroll
        for (int q = 0; q < 4; q++) {
            float v = __uint_as_float(ee[q].y);
            float2 a = __half22float2(*(__half2*)&dd[q].x);
            float2 b = __half22float2(*(__half2*)&dd[q].y);
            if (q & 1) {
                acc1.x += v * a.x; acc1.y += v * a.y;
                acc1.z += v * b.x; acc1.w += v * b.y;
            } else {
                acc0.x += v * a.x; acc0.y += v * a.y;
                acc0.z += v * b.x; acc0.w += v * b.y;
            }
        }
        j += 4;
    }
    for (; j < e; j++) {
        uint2 e0 = __ldg(&g_edges[j]);
        uint2 d0 = __ldg(&sup[(size_t)e0.x * 32 + lane]);
        float v0 = __uint_as_float(e0.y);
        float2 a = __half22float2(*(__half2*)&d0.x);
        float2 b = __half22float2(*(__half2*)&d0.y);
        acc0.x += v0 * a.x; acc0.y += v0 * a.y; acc0.z += v0 * b.x; acc0.w += v0 * b.y;
    }

    float4 o;
    o.x = fmaxf(acc0.x + acc1.x, 0.f);
    o.y = fmaxf(acc0.y + acc1.y, 0.f);
    o.z = fmaxf(acc0.z + acc1.z, 0.f);
    o.w = fmaxf(acc0.w + acc1.w, 0.f);
    __stcs((float4*)(out + (size_t)row * N_OUT) + lane, o);
}

// ---------------------------------------------------------------------------
// Side stream (LOW priority: CSR yields SM slots to the critical GEMM branch)
// + fork/join events. Created once at load time.
// ---------------------------------------------------------------------------
static cudaStream_t g_s2   = nullptr;
static cudaEvent_t  g_fork = nullptr;
static cudaEvent_t  g_join = nullptr;
namespace {
struct StreamInit {
    StreamInit() {
        int lo = 0, hi = 0;
        cudaDeviceGetStreamPriorityRange(&lo, &hi);   // lo = least priority
        if (cudaStreamCreateWithPriority(&g_s2, cudaStreamNonBlocking, lo) != cudaSuccess)
            g_s2 = nullptr;
        if (cudaEventCreateWithFlags(&g_fork, cudaEventDisableTiming) != cudaSuccess) g_fork = nullptr;
        if (cudaEventCreateWithFlags(&g_join, cudaEventDisableTiming) != cudaSuccess) g_join = nullptr;
    }
};
static StreamInit g_streamInit;
}

// ---------------------------------------------------------------------------
extern "C" void kernel_launch(void* const* d_in, const int* in_sizes, int n_in,
                              void* d_out, int out_size)
{
    const float* x    = (const float*)d_in[0];
    const int*   erow = (const int*)  d_in[1];
    const int*   ecol = (const int*)  d_in[2];
    const float* eval = (const float*)d_in[3];
    const float* W    = (const float*)d_in[4];
    const float* bias = (const float*)d_in[5];
    float* out = (float*)d_out;

    const int E  = in_sizes[1];
    const int nb = (M_NODES + SCAN_BS - 1) / SCAN_BS;   // 98

    const int GEMM_SMEM = (3 * 128 * 40 + 3 * 16 * 136) * 4;   // 87552 B
    cudaFuncSetAttribute(gemm_fp16_kernel,
                         cudaFuncAttributeMaxDynamicSharedMemorySize, GEMM_SMEM);

    const bool fork = (g_s2 && g_fork && g_join);
    cudaStream_t s2 = fork ? g_s2 : (cudaStream_t)0;

    if (fork) {
        cudaEventRecord(g_fork, 0);
        cudaStreamWaitEvent(s2, g_fork, 0);
    }

    // ---- branch B FIRST (main stream, critical path): GEMM ----
    wconv_kernel<<<((K_IN / 2) * N_OUT + 255) / 256, 256>>>(W);
    gemm_fp16_kernel<<<(M_NODES + 127) / 128, 256, GEMM_SMEM>>>(x, bias);

    // ---- branch A (low-priority side stream): CSR build ----
    hist_kernel<<<(E + 255) / 256, 256, 0, s2>>>(erow, E);
    scan_lookback_kernel<<<nb, SCAN_BS, 0, s2>>>(M_NODES, E);
    permute_kernel<<<(E + 255) / 256, 256, 0, s2>>>(erow, ecol, eval, E);

    if (fork) cudaEventRecord(g_join, s2);

    // ---- join, then gather ----
    if (fork) cudaStreamWaitEvent(0, g_join, 0);
    gather_kernel<<<(M_NODES * 32 + 255) / 256, 256>>>(out);
}